// round 14
// baseline (speedup 1.0000x reference)
#include <cuda_runtime.h>
#include <cuda_fp16.h>
#include <cstdint>

// Conv2D 3x3 s1 p1: x[8,16,512,512] fp32 * w[16,144] -> out[8,16,512,512]
// Implicit GEMM on mma.sync.m16n8k16 (f16, f32 acc), persistent CTAs.
// R12: warp-specialized producer/consumer (R11) with the right-halo off-by-one
// FIXED: ns[xx] <-> gx = x0 + xx - 1, so xx=32+lane loads gx = x0+31+lane.
// 8 consumer warps (R9 compute core) vs 4 producer warps (LDG->cvt->STS),
// double-buffered ns, mbarrier full/empty handshake, no consumer barriers.

#define HW      512
#define NSX     34
#define NSY     18
#define CPAD    24       // ci stride (halves): 48B rows, LDSM conflict-free
#define NTILES  4096
#define GRID    304      // 2 CTAs/SM x 152 SMs
#define NTHR    384      // 8 consumer + 4 producer warps

#define NS_SZ    29376                     // 18*34*24*2 bytes
#define BS_OFF   (2 * NS_SZ)               // 58752; Bs2: 4608 B
#define MB_OFF   (BS_OFF + 4608)           // 63360; 4 mbarriers
#define SM_TOTAL (MB_OFF + 32)

static __device__ __forceinline__ void mma16816(float* c, uint32_t a0, uint32_t a1,
                                                uint32_t a2, uint32_t a3,
                                                uint32_t b0, uint32_t b1) {
    asm volatile(
        "mma.sync.aligned.m16n8k16.row.col.f32.f16.f16.f32 "
        "{%0,%1,%2,%3}, {%4,%5,%6,%7}, {%8,%9}, {%0,%1,%2,%3};"
        : "+f"(c[0]), "+f"(c[1]), "+f"(c[2]), "+f"(c[3])
        : "r"(a0), "r"(a1), "r"(a2), "r"(a3), "r"(b0), "r"(b1));
}

static __device__ __forceinline__ void ldsm4(uint32_t& a0, uint32_t& a1,
                                             uint32_t& a2, uint32_t& a3, uint32_t addr) {
    asm volatile("ldmatrix.sync.aligned.m8n8.x4.shared.b16 {%0,%1,%2,%3}, [%4];"
                 : "=r"(a0), "=r"(a1), "=r"(a2), "=r"(a3) : "r"(addr));
}

static __device__ __forceinline__ uint32_t smem_u32(const void* p) {
    uint32_t a;
    asm("{ .reg .u64 t; cvta.to.shared.u64 t, %1; cvt.u32.u64 %0, t; }" : "=r"(a) : "l"(p));
    return a;
}

static __device__ __forceinline__ bool elect_one() {
    uint32_t p;
    asm volatile("{ .reg .pred p; elect.sync _|p, 0xFFFFFFFF; selp.b32 %0, 1, 0, p; }"
                 : "=r"(p));
    return p != 0;
}

static __device__ __forceinline__ void mbar_wait(uint32_t mbar, uint32_t parity) {
    uint32_t done;
    asm volatile(
        "{\n\t.reg .pred p;\n\t"
        "mbarrier.try_wait.parity.acquire.cta.shared::cta.b64 p, [%1], %2;\n\t"
        "selp.b32 %0, 1, 0, p;\n\t}"
        : "=r"(done) : "r"(mbar), "r"(parity) : "memory");
    if (!done) {
        asm volatile(
            "{\n\t.reg .pred P1;\n\tWL_%=: \n\t"
            "mbarrier.try_wait.parity.acquire.cta.shared::cta.b64 P1, [%0], %1, 0x989680;\n\t"
            "@P1 bra.uni WD_%=;\n\tbra.uni WL_%=;\n\tWD_%=: \n\t}"
            :: "r"(mbar), "r"(parity) : "memory");
    }
}

static __device__ __forceinline__ void mbar_arrive(uint32_t mbar) {
    asm volatile("mbarrier.arrive.release.cta.shared::cta.b64 _, [%0];"
                 :: "r"(mbar) : "memory");
}

__global__ __launch_bounds__(NTHR, 2)
void conv_mma_ws(const float* __restrict__ xin,
                 const float* __restrict__ wgt,
                 float* __restrict__ out)
{
    extern __shared__ __align__(16) char smem[];
    __half* ns0 = (__half*)smem;
    uint2*  Bs2 = (uint2*)(smem + BS_OFF);
    const uint32_t sbase = smem_u32(smem);
    const uint32_t mbF0 = sbase + MB_OFF;
    const uint32_t mbF1 = mbF0 + 8;
    const uint32_t mbE0 = mbF0 + 16;
    const uint32_t mbE1 = mbF0 + 24;

    const int t    = threadIdx.x;
    const int lane = t & 31;
    const int wrp  = t >> 5;

    // ---- init: weights + mbarriers ----
    #pragma unroll
    for (int e = t; e < 576; e += NTHR) {
        const int slot = e >> 5, l2 = e & 31;
        const int g2 = l2 >> 2, cq2 = (l2 & 3) * 2;
        const int nn = slot & 1, kwk = (slot >> 1) % 3, dy = slot / 6;
        const float* wb = wgt + (nn * 8 + g2) * 144 + dy * 3 + kwk;
        __half2 w0 = __floats2half2_rn(wb[cq2 * 9],       wb[(cq2 + 1) * 9]);
        __half2 w1 = __floats2half2_rn(wb[(cq2 + 8) * 9], wb[(cq2 + 9) * 9]);
        uint2 v;
        v.x = *(const uint32_t*)&w0;
        v.y = *(const uint32_t*)&w1;
        Bs2[e] = v;
    }
    if (t == 0) {
        asm volatile("mbarrier.init.shared.b64 [%0], 4;" :: "r"(mbF0) : "memory");
        asm volatile("mbarrier.init.shared.b64 [%0], 4;" :: "r"(mbF1) : "memory");
        asm volatile("mbarrier.init.shared.b64 [%0], 8;" :: "r"(mbE0) : "memory");
        asm volatile("mbarrier.init.shared.b64 [%0], 8;" :: "r"(mbE1) : "memory");
    }
    __syncthreads();

    if (wrp >= 8) {
        // ================= PRODUCER (warps 8-11) =================
        const int pw = wrp - 8;
        uint32_t pph0 = 0, pph1 = 0;
        int it = 0;
        for (int tile = blockIdx.x; tile < NTILES; tile += GRID, ++it) {
            const int b = it & 1;
            const int x0 = (tile & 15) * 32, y0 = ((tile >> 4) & 31) * 16, n = tile >> 9;
            if (it >= 2) {
                if (b == 0) { mbar_wait(mbE0, pph0); pph0 ^= 1; }
                else        { mbar_wait(mbE1, pph1); pph1 ^= 1; }
            }
            __half* ns = ns0 + b * (NS_SZ / 2);

            #pragma unroll
            for (int j = 0; j < 2; ++j) {
                const int cp  = pw + 4 * j;      // ci pair 0..7
                const int ci0 = 2 * cp;
                const float* s0 = xin + (size_t)(n * 16 + ci0) * HW * HW;
                const float* s1 = s0 + (size_t)HW * HW;
                const int gxA = x0 + lane - 1;               // ns xx = lane
                const bool okA = (unsigned)gxA < HW;
                const int gxB = x0 + 31 + lane;              // ns xx = 32+lane  (FIX)
                const bool hasB = (lane < 2);
                const bool okB = hasB && ((unsigned)gxB < HW);
                #pragma unroll 3
                for (int yy = 0; yy < NSY; ++yy) {
                    const int gy = y0 + yy - 1;
                    const bool okY = (unsigned)gy < HW;
                    const size_t ro = (size_t)(okY ? gy : 0) * HW;
                    float a0 = 0.f, a1 = 0.f;
                    if (okY && okA) { a0 = s0[ro + gxA]; a1 = s1[ro + gxA]; }
                    *(__half2*)&ns[(yy * NSX + lane) * CPAD + ci0] =
                        __floats2half2_rn(a0, a1);
                    if (hasB) {
                        float b0 = 0.f, b1 = 0.f;
                        if (okY && okB) { b0 = s0[ro + gxB]; b1 = s1[ro + gxB]; }
                        *(__half2*)&ns[(yy * NSX + 32 + lane) * CPAD + ci0] =
                            __floats2half2_rn(b0, b1);
                    }
                }
            }
            if (elect_one()) mbar_arrive(b == 0 ? mbF0 : mbF1);
        }
    } else {
        // ================= CONSUMER (warps 0-7): R9 compute core =================
        const int g  = lane >> 2;
        const int cq = (lane & 3) * 2;
        const uint32_t fbb = sbase + (uint32_t)(((lane & 15) * CPAD + (lane >> 4) * 8) * 2);
        uint32_t cph0 = 0, cph1 = 0;
        int it = 0;
        for (int tile = blockIdx.x; tile < NTILES; tile += GRID, ++it) {
            const int b = it & 1;
            const int x0 = (tile & 15) * 32, y0 = ((tile >> 4) & 31) * 16, n = tile >> 9;
            if (b == 0) { mbar_wait(mbF0, cph0); cph0 ^= 1; }
            else        { mbar_wait(mbF1, cph1); cph1 ^= 1; }
            const uint32_t fb = fbb + (uint32_t)(b * NS_SZ);

            float acc[4][2][4];
            #pragma unroll
            for (int i = 0; i < 4; ++i)
                #pragma unroll
                for (int nn = 0; nn < 2; ++nn)
                    #pragma unroll
                    for (int j = 0; j < 4; ++j) acc[i][nn][j] = 0.0f;

            #pragma unroll
            for (int kw = 0; kw < 3; ++kw) {
                uint32_t bf[3][2][2];
                #pragma unroll
                for (int dy = 0; dy < 3; ++dy)
                    #pragma unroll
                    for (int nn = 0; nn < 2; ++nn) {
                        uint2 v = Bs2[((dy * 3 + kw) * 2 + nn) * 32 + lane];
                        bf[dy][nn][0] = v.x;
                        bf[dy][nn][1] = v.y;
                    }
                #pragma unroll
                for (int xh = 0; xh < 2; ++xh) {
                    uint32_t F[4][4];
                    #pragma unroll
                    for (int q = 0; q < 4; ++q)
                        ldsm4(F[q][0], F[q][1], F[q][2], F[q][3],
                              fb + (uint32_t)(((2 * wrp + q) * NSX + xh * 16 + kw)
                                              * (CPAD * 2)));
                    #pragma unroll
                    for (int yl = 0; yl < 2; ++yl)
                        #pragma unroll
                        for (int dy = 0; dy < 3; ++dy) {
                            const int q = yl + dy;
                            const int i = yl * 2 + xh;
                            mma16816(acc[i][0], F[q][0], F[q][1], F[q][2], F[q][3],
                                     bf[dy][0][0], bf[dy][0][1]);
                            mma16816(acc[i][1], F[q][0], F[q][1], F[q][2], F[q][3],
                                     bf[dy][1][0], bf[dy][1][1]);
                        }
                }
            }
            if (elect_one()) mbar_arrive(b == 0 ? mbE0 : mbE1);

            // ---- direct-store epilogue ----
            #pragma unroll
            for (int i = 0; i < 4; ++i) {
                const int yloc = wrp * 2 + (i >> 1);
                const int xh   = i & 1;
                const int y  = y0 + yloc;
                const int xg = x0 + xh * 16 + g;
                #pragma unroll
                for (int nn = 0; nn < 2; ++nn) {
                    const int co = nn * 8 + cq;
                    float* op = out + ((size_t)(n * 16 + co) * HW + y) * HW + xg;
                    op[0]                   = acc[i][nn][0];
                    op[(size_t)HW * HW]     = acc[i][nn][1];
                    op[8]                   = acc[i][nn][2];
                    op[(size_t)HW * HW + 8] = acc[i][nn][3];
                }
            }
        }
    }
}

extern "C" void kernel_launch(void* const* d_in, const int* in_sizes, int n_in,
                              void* d_out, int out_size) {
    const float* x = (const float*)d_in[0];   // [8,16,512,512]
    const float* w = (const float*)d_in[1];   // [16,144]
    float* out = (float*)d_out;

    static int attr_done = 0;
    if (!attr_done) {
        cudaFuncSetAttribute(conv_mma_ws,
                             cudaFuncAttributeMaxDynamicSharedMemorySize, SM_TOTAL);
        attr_done = 1;
    }
    conv_mma_ws<<<GRID, NTHR, SM_TOTAL>>>(x, w, out);
}

// round 15
// speedup vs baseline: 4.9930x; 4.9930x over previous
#include <cuda_runtime.h>
#include <cuda_fp16.h>
#include <cstdint>

// Conv2D 3x3 s1 p1: x[8,16,512,512] fp32 * w[16,144] -> out[8,16,512,512]
// Implicit GEMM on mma.sync.m16n8k16 (f16, f32 acc), persistent CTAs.
// R13: warp-specialized producer/consumer (R12) with MLP-batched producer:
// each 9-row chunk issues all its LDGs into registers first (one exposed
// gmem latency per chunk), then cvt+STS. Consumer core unchanged (R9).
// 8 consumer + 4 producer warps, double-buffered ns, mbarrier handshake.

#define HW      512
#define NSX     34
#define NSY     18
#define CPAD    24       // ci stride (halves): 48B rows, LDSM conflict-free
#define NTILES  4096
#define GRID    304      // 2 CTAs/SM x 152 SMs
#define NTHR    384      // 8 consumer + 4 producer warps

#define NS_SZ    29376                     // 18*34*24*2 bytes
#define BS_OFF   (2 * NS_SZ)               // 58752; Bs2: 4608 B
#define MB_OFF   (BS_OFF + 4608)           // 63360; 4 mbarriers
#define SM_TOTAL (MB_OFF + 32)

static __device__ __forceinline__ void mma16816(float* c, uint32_t a0, uint32_t a1,
                                                uint32_t a2, uint32_t a3,
                                                uint32_t b0, uint32_t b1) {
    asm volatile(
        "mma.sync.aligned.m16n8k16.row.col.f32.f16.f16.f32 "
        "{%0,%1,%2,%3}, {%4,%5,%6,%7}, {%8,%9}, {%0,%1,%2,%3};"
        : "+f"(c[0]), "+f"(c[1]), "+f"(c[2]), "+f"(c[3])
        : "r"(a0), "r"(a1), "r"(a2), "r"(a3), "r"(b0), "r"(b1));
}

static __device__ __forceinline__ void ldsm4(uint32_t& a0, uint32_t& a1,
                                             uint32_t& a2, uint32_t& a3, uint32_t addr) {
    asm volatile("ldmatrix.sync.aligned.m8n8.x4.shared.b16 {%0,%1,%2,%3}, [%4];"
                 : "=r"(a0), "=r"(a1), "=r"(a2), "=r"(a3) : "r"(addr));
}

static __device__ __forceinline__ uint32_t smem_u32(const void* p) {
    uint32_t a;
    asm("{ .reg .u64 t; cvta.to.shared.u64 t, %1; cvt.u32.u64 %0, t; }" : "=r"(a) : "l"(p));
    return a;
}

static __device__ __forceinline__ bool elect_one() {
    uint32_t p;
    asm volatile("{ .reg .pred p; elect.sync _|p, 0xFFFFFFFF; selp.b32 %0, 1, 0, p; }"
                 : "=r"(p));
    return p != 0;
}

static __device__ __forceinline__ void mbar_wait(uint32_t mbar, uint32_t parity) {
    uint32_t done;
    asm volatile(
        "{\n\t.reg .pred p;\n\t"
        "mbarrier.try_wait.parity.acquire.cta.shared::cta.b64 p, [%1], %2;\n\t"
        "selp.b32 %0, 1, 0, p;\n\t}"
        : "=r"(done) : "r"(mbar), "r"(parity) : "memory");
    if (!done) {
        asm volatile(
            "{\n\t.reg .pred P1;\n\tWL_%=: \n\t"
            "mbarrier.try_wait.parity.acquire.cta.shared::cta.b64 P1, [%0], %1, 0x989680;\n\t"
            "@P1 bra.uni WD_%=;\n\tbra.uni WL_%=;\n\tWD_%=: \n\t}"
            :: "r"(mbar), "r"(parity) : "memory");
    }
}

static __device__ __forceinline__ void mbar_arrive(uint32_t mbar) {
    asm volatile("mbarrier.arrive.release.cta.shared::cta.b64 _, [%0];"
                 :: "r"(mbar) : "memory");
}

__global__ __launch_bounds__(NTHR, 2)
void conv_mma_ws(const float* __restrict__ xin,
                 const float* __restrict__ wgt,
                 float* __restrict__ out)
{
    extern __shared__ __align__(16) char smem[];
    __half* ns0 = (__half*)smem;
    uint2*  Bs2 = (uint2*)(smem + BS_OFF);
    const uint32_t sbase = smem_u32(smem);
    const uint32_t mbF0 = sbase + MB_OFF;
    const uint32_t mbF1 = mbF0 + 8;
    const uint32_t mbE0 = mbF0 + 16;
    const uint32_t mbE1 = mbF0 + 24;

    const int t    = threadIdx.x;
    const int lane = t & 31;
    const int wrp  = t >> 5;

    // ---- init: weights + mbarriers ----
    #pragma unroll
    for (int e = t; e < 576; e += NTHR) {
        const int slot = e >> 5, l2 = e & 31;
        const int g2 = l2 >> 2, cq2 = (l2 & 3) * 2;
        const int nn = slot & 1, kwk = (slot >> 1) % 3, dy = slot / 6;
        const float* wb = wgt + (nn * 8 + g2) * 144 + dy * 3 + kwk;
        __half2 w0 = __floats2half2_rn(wb[cq2 * 9],       wb[(cq2 + 1) * 9]);
        __half2 w1 = __floats2half2_rn(wb[(cq2 + 8) * 9], wb[(cq2 + 9) * 9]);
        uint2 v;
        v.x = *(const uint32_t*)&w0;
        v.y = *(const uint32_t*)&w1;
        Bs2[e] = v;
    }
    if (t == 0) {
        asm volatile("mbarrier.init.shared.b64 [%0], 4;" :: "r"(mbF0) : "memory");
        asm volatile("mbarrier.init.shared.b64 [%0], 4;" :: "r"(mbF1) : "memory");
        asm volatile("mbarrier.init.shared.b64 [%0], 8;" :: "r"(mbE0) : "memory");
        asm volatile("mbarrier.init.shared.b64 [%0], 8;" :: "r"(mbE1) : "memory");
    }
    __syncthreads();

    if (wrp >= 8) {
        // ================= PRODUCER (warps 8-11), MLP-batched =================
        const int pw = wrp - 8;
        uint32_t pph0 = 0, pph1 = 0;
        int it = 0;
        for (int tile = blockIdx.x; tile < NTILES; tile += GRID, ++it) {
            const int b = it & 1;
            const int x0 = (tile & 15) * 32, y0 = ((tile >> 4) & 31) * 16, n = tile >> 9;
            if (it >= 2) {
                if (b == 0) { mbar_wait(mbE0, pph0); pph0 ^= 1; }
                else        { mbar_wait(mbE1, pph1); pph1 ^= 1; }
            }
            __half* ns = ns0 + b * (NS_SZ / 2);

            const int gxA = x0 + lane - 1;               // ns xx = lane
            const bool okA = (unsigned)gxA < HW;
            const int gxB = x0 + 31 + lane;              // ns xx = 32+lane
            const bool hasB = (lane < 2);
            const bool okB = hasB && ((unsigned)gxB < HW);

            #pragma unroll
            for (int j = 0; j < 2; ++j) {
                const int ci0 = 2 * (pw + 4 * j);
                const float* s0 = xin + (size_t)(n * 16 + ci0) * HW * HW;
                const float* s1 = s0 + (size_t)HW * HW;
                #pragma unroll
                for (int half = 0; half < 2; ++half) {
                    const int yb = half * 9;
                    // -- batch-issue all loads for 9 rows (regs) --
                    float a0[9], a1[9], b0[9], b1[9];
                    #pragma unroll
                    for (int r = 0; r < 9; ++r) {
                        const int gy = y0 + yb + r - 1;
                        const bool okY = (unsigned)gy < HW;
                        const size_t ro = (size_t)(okY ? gy : 0) * HW;
                        const bool oA = okY && okA;
                        const bool oB = okY && okB;
                        a0[r] = oA ? s0[ro + gxA] : 0.f;
                        a1[r] = oA ? s1[ro + gxA] : 0.f;
                        b0[r] = oB ? s0[ro + gxB] : 0.f;
                        b1[r] = oB ? s1[ro + gxB] : 0.f;
                    }
                    // -- cvt + STS --
                    #pragma unroll
                    for (int r = 0; r < 9; ++r) {
                        const int yy = yb + r;
                        *(__half2*)&ns[(yy * NSX + lane) * CPAD + ci0] =
                            __floats2half2_rn(a0[r], a1[r]);
                        if (hasB)
                            *(__half2*)&ns[(yy * NSX + 32 + lane) * CPAD + ci0] =
                                __floats2half2_rn(b0[r], b1[r]);
                    }
                }
            }
            if (elect_one()) mbar_arrive(b == 0 ? mbF0 : mbF1);
        }
    } else {
        // ================= CONSUMER (warps 0-7): R9 compute core =================
        const int g  = lane >> 2;
        const int cq = (lane & 3) * 2;
        const uint32_t fbb = sbase + (uint32_t)(((lane & 15) * CPAD + (lane >> 4) * 8) * 2);
        uint32_t cph0 = 0, cph1 = 0;
        int it = 0;
        for (int tile = blockIdx.x; tile < NTILES; tile += GRID, ++it) {
            const int b = it & 1;
            const int x0 = (tile & 15) * 32, y0 = ((tile >> 4) & 31) * 16, n = tile >> 9;
            if (b == 0) { mbar_wait(mbF0, cph0); cph0 ^= 1; }
            else        { mbar_wait(mbF1, cph1); cph1 ^= 1; }
            const uint32_t fb = fbb + (uint32_t)(b * NS_SZ);

            float acc[4][2][4];
            #pragma unroll
            for (int i = 0; i < 4; ++i)
                #pragma unroll
                for (int nn = 0; nn < 2; ++nn)
                    #pragma unroll
                    for (int j = 0; j < 4; ++j) acc[i][nn][j] = 0.0f;

            #pragma unroll
            for (int kw = 0; kw < 3; ++kw) {
                uint32_t bf[3][2][2];
                #pragma unroll
                for (int dy = 0; dy < 3; ++dy)
                    #pragma unroll
                    for (int nn = 0; nn < 2; ++nn) {
                        uint2 v = Bs2[((dy * 3 + kw) * 2 + nn) * 32 + lane];
                        bf[dy][nn][0] = v.x;
                        bf[dy][nn][1] = v.y;
                    }
                #pragma unroll
                for (int xh = 0; xh < 2; ++xh) {
                    uint32_t F[4][4];
                    #pragma unroll
                    for (int q = 0; q < 4; ++q)
                        ldsm4(F[q][0], F[q][1], F[q][2], F[q][3],
                              fb + (uint32_t)(((2 * wrp + q) * NSX + xh * 16 + kw)
                                              * (CPAD * 2)));
                    #pragma unroll
                    for (int yl = 0; yl < 2; ++yl)
                        #pragma unroll
                        for (int dy = 0; dy < 3; ++dy) {
                            const int q = yl + dy;
                            const int i = yl * 2 + xh;
                            mma16816(acc[i][0], F[q][0], F[q][1], F[q][2], F[q][3],
                                     bf[dy][0][0], bf[dy][0][1]);
                            mma16816(acc[i][1], F[q][0], F[q][1], F[q][2], F[q][3],
                                     bf[dy][1][0], bf[dy][1][1]);
                        }
                }
            }
            if (elect_one()) mbar_arrive(b == 0 ? mbE0 : mbE1);

            // ---- direct-store epilogue ----
            #pragma unroll
            for (int i = 0; i < 4; ++i) {
                const int yloc = wrp * 2 + (i >> 1);
                const int xh   = i & 1;
                const int y  = y0 + yloc;
                const int xg = x0 + xh * 16 + g;
                #pragma unroll
                for (int nn = 0; nn < 2; ++nn) {
                    const int co = nn * 8 + cq;
                    float* op = out + ((size_t)(n * 16 + co) * HW + y) * HW + xg;
                    op[0]                   = acc[i][nn][0];
                    op[(size_t)HW * HW]     = acc[i][nn][1];
                    op[8]                   = acc[i][nn][2];
                    op[(size_t)HW * HW + 8] = acc[i][nn][3];
                }
            }
        }
    }
}

extern "C" void kernel_launch(void* const* d_in, const int* in_sizes, int n_in,
                              void* d_out, int out_size) {
    const float* x = (const float*)d_in[0];   // [8,16,512,512]
    const float* w = (const float*)d_in[1];   // [16,144]
    float* out = (float*)d_out;

    static int attr_done = 0;
    if (!attr_done) {
        cudaFuncSetAttribute(conv_mma_ws,
                             cudaFuncAttributeMaxDynamicSharedMemorySize, SM_TOTAL);
        attr_done = 1;
    }
    conv_mma_ws<<<GRID, NTHR, SM_TOTAL>>>(x, w, out);
}

// round 17
// speedup vs baseline: 6.4622x; 1.2942x over previous
#include <cuda_runtime.h>
#include <cuda_fp16.h>
#include <cstdint>

// Conv2D 3x3 s1 p1: x[8,16,512,512] fp32 * w[16,144] -> out[8,16,512,512]
// Implicit GEMM on mma.sync.m16n8k16 (f16, f32 acc), persistent CTAs.
// R14: warp-specialized (R13) + conflict-free producer stores. Producer warp
// owns a ci OCTET (8 channels) x 9 rows: lane loads 8 floats (one per plane,
// coalesced) and writes ONE STS.128 -> 8 lanes/phase at 48B stride = 8 distinct
// banks, no conflicts (was 4-way on STS.32). Halo xx=32,33 via st.shared.u16.
// Consumer core (R9) and handshake unchanged.

#define HW      512
#define PLANE   (HW * HW)
#define NSX     34
#define NSY     18
#define CPAD    24       // ci stride (halves): 48B rows, LDSM conflict-free
#define NTILES  4096
#define GRID    304      // 2 CTAs/SM x 152 SMs
#define NTHR    384      // 8 consumer + 4 producer warps

#define NS_SZ    29376                     // 18*34*24*2 bytes
#define BS_OFF   (2 * NS_SZ)               // 58752; Bs2: 4608 B
#define MB_OFF   (BS_OFF + 4608)           // 63360; 4 mbarriers
#define SM_TOTAL (MB_OFF + 32)

static __device__ __forceinline__ void mma16816(float* c, uint32_t a0, uint32_t a1,
                                                uint32_t a2, uint32_t a3,
                                                uint32_t b0, uint32_t b1) {
    asm volatile(
        "mma.sync.aligned.m16n8k16.row.col.f32.f16.f16.f32 "
        "{%0,%1,%2,%3}, {%4,%5,%6,%7}, {%8,%9}, {%0,%1,%2,%3};"
        : "+f"(c[0]), "+f"(c[1]), "+f"(c[2]), "+f"(c[3])
        : "r"(a0), "r"(a1), "r"(a2), "r"(a3), "r"(b0), "r"(b1));
}

static __device__ __forceinline__ void ldsm4(uint32_t& a0, uint32_t& a1,
                                             uint32_t& a2, uint32_t& a3, uint32_t addr) {
    asm volatile("ldmatrix.sync.aligned.m8n8.x4.shared.b16 {%0,%1,%2,%3}, [%4];"
                 : "=r"(a0), "=r"(a1), "=r"(a2), "=r"(a3) : "r"(addr));
}

static __device__ __forceinline__ uint32_t smem_u32(const void* p) {
    uint32_t a;
    asm("{ .reg .u64 t; cvta.to.shared.u64 t, %1; cvt.u32.u64 %0, t; }" : "=r"(a) : "l"(p));
    return a;
}

static __device__ __forceinline__ bool elect_one() {
    uint32_t p;
    asm volatile("{ .reg .pred p; elect.sync _|p, 0xFFFFFFFF; selp.b32 %0, 1, 0, p; }"
                 : "=r"(p));
    return p != 0;
}

static __device__ __forceinline__ void mbar_wait(uint32_t mbar, uint32_t parity) {
    uint32_t done;
    asm volatile(
        "{\n\t.reg .pred p;\n\t"
        "mbarrier.try_wait.parity.acquire.cta.shared::cta.b64 p, [%1], %2;\n\t"
        "selp.b32 %0, 1, 0, p;\n\t}"
        : "=r"(done) : "r"(mbar), "r"(parity) : "memory");
    if (!done) {
        asm volatile(
            "{\n\t.reg .pred P1;\n\tWL_%=: \n\t"
            "mbarrier.try_wait.parity.acquire.cta.shared::cta.b64 P1, [%0], %1, 0x989680;\n\t"
            "@P1 bra.uni WD_%=;\n\tbra.uni WL_%=;\n\tWD_%=: \n\t}"
            :: "r"(mbar), "r"(parity) : "memory");
    }
}

static __device__ __forceinline__ void mbar_arrive(uint32_t mbar) {
    asm volatile("mbarrier.arrive.release.cta.shared::cta.b64 _, [%0];"
                 :: "r"(mbar) : "memory");
}

__global__ __launch_bounds__(NTHR, 2)
void conv_mma_ws(const float* __restrict__ xin,
                 const float* __restrict__ wgt,
                 float* __restrict__ out)
{
    extern __shared__ __align__(16) char smem[];
    __half* ns0 = (__half*)smem;
    uint2*  Bs2 = (uint2*)(smem + BS_OFF);
    const uint32_t sbase = smem_u32(smem);
    const uint32_t mbF0 = sbase + MB_OFF;
    const uint32_t mbF1 = mbF0 + 8;
    const uint32_t mbE0 = mbF0 + 16;
    const uint32_t mbE1 = mbF0 + 24;

    const int t    = threadIdx.x;
    const int lane = t & 31;
    const int wrp  = t >> 5;

    // ---- init: weights + mbarriers ----
    #pragma unroll
    for (int e = t; e < 576; e += NTHR) {
        const int slot = e >> 5, l2 = e & 31;
        const int g2 = l2 >> 2, cq2 = (l2 & 3) * 2;
        const int nn = slot & 1, kwk = (slot >> 1) % 3, dy = slot / 6;
        const float* wb = wgt + (nn * 8 + g2) * 144 + dy * 3 + kwk;
        __half2 w0 = __floats2half2_rn(wb[cq2 * 9],       wb[(cq2 + 1) * 9]);
        __half2 w1 = __floats2half2_rn(wb[(cq2 + 8) * 9], wb[(cq2 + 9) * 9]);
        uint2 v;
        v.x = *(const uint32_t*)&w0;
        v.y = *(const uint32_t*)&w1;
        Bs2[e] = v;
    }
    if (t == 0) {
        asm volatile("mbarrier.init.shared.b64 [%0], 4;" :: "r"(mbF0) : "memory");
        asm volatile("mbarrier.init.shared.b64 [%0], 4;" :: "r"(mbF1) : "memory");
        asm volatile("mbarrier.init.shared.b64 [%0], 8;" :: "r"(mbE0) : "memory");
        asm volatile("mbarrier.init.shared.b64 [%0], 8;" :: "r"(mbE1) : "memory");
    }
    __syncthreads();

    if (wrp >= 8) {
        // ======== PRODUCER (warps 8-11): ci-octet x 9-row ownership ========
        const int pw    = wrp - 8;
        const int octet = pw & 1;            // ci 8*octet .. 8*octet+7
        const int ci0   = octet * 8;
        const int rlo   = (pw >> 1) * 9;     // rows rlo .. rlo+8
        const int hc    = lane & 7;          // halo ci within octet (lanes 0-7)

        uint32_t pph0 = 0, pph1 = 0;
        int it = 0;
        for (int tile = blockIdx.x; tile < NTILES; tile += GRID, ++it) {
            const int b = it & 1;
            const int x0 = (tile & 15) * 32, y0 = ((tile >> 4) & 31) * 16, n = tile >> 9;
            if (it >= 2) {
                if (b == 0) { mbar_wait(mbE0, pph0); pph0 ^= 1; }
                else        { mbar_wait(mbE1, pph1); pph1 ^= 1; }
            }
            __half* ns = ns0 + b * (NS_SZ / 2);

            const float* base = xin + (size_t)(n * 16 + ci0) * PLANE;
            const int gxA = x0 + lane - 1;               // ns xx = lane
            const bool okA = (unsigned)gxA < HW;
            const bool isH = (lane < 8);                 // halo crew: lanes 0-7
            const int gxH = x0 + 31;                     // xx=32; xx=33 is gxH+1
            const bool hasR = (x0 < 480);                // xx=33 in-image?

            #pragma unroll
            for (int rb = 0; rb < 3; ++rb) {
                float v[3][8];
                float h32[3], h33[3];
                // -- batch-issue all loads for 3 rows (MLP ~24) --
                #pragma unroll
                for (int r2 = 0; r2 < 3; ++r2) {
                    const int gy = y0 + rlo + rb * 3 + r2 - 1;
                    const bool okY = (unsigned)gy < HW;
                    const size_t ro = (size_t)(okY ? gy : 0) * HW;
                    const bool oA = okY && okA;
                    const float* sA = base + ro + gxA;
                    #pragma unroll
                    for (int c = 0; c < 8; ++c)
                        v[r2][c] = oA ? sA[c * PLANE] : 0.f;
                    const float* sH = base + (size_t)hc * PLANE + ro + gxH;
                    h32[r2] = (okY && isH) ? sH[0] : 0.f;
                    h33[r2] = (okY && isH && hasR) ? sH[1] : 0.f;
                }
                // -- cvt + conflict-free stores --
                #pragma unroll
                for (int r2 = 0; r2 < 3; ++r2) {
                    const int yy = rlo + rb * 3 + r2;
                    __half2 h[4];
                    #pragma unroll
                    for (int k = 0; k < 4; ++k)
                        h[k] = __floats2half2_rn(v[r2][2 * k], v[r2][2 * k + 1]);
                    *(uint4*)&ns[(yy * NSX + lane) * CPAD + ci0] = *(uint4*)h;
                    if (isH) {
                        const uint32_t ha = sbase + (uint32_t)(b * NS_SZ) +
                            (uint32_t)(((yy * NSX + 32) * CPAD + ci0 + hc) * 2);
                        unsigned short u32b = __half_as_ushort(__float2half_rn(h32[r2]));
                        unsigned short u33b = __half_as_ushort(__float2half_rn(h33[r2]));
                        asm volatile("st.shared.u16 [%0], %1;" :: "r"(ha), "h"(u32b)
                                     : "memory");
                        asm volatile("st.shared.u16 [%0], %1;"
                                     :: "r"(ha + CPAD * 2), "h"(u33b) : "memory");
                    }
                }
            }
            if (elect_one()) mbar_arrive(b == 0 ? mbF0 : mbF1);
        }
    } else {
        // ================= CONSUMER (warps 0-7): R9 compute core =================
        const int g  = lane >> 2;
        const int cq = (lane & 3) * 2;
        const uint32_t fbb = sbase + (uint32_t)(((lane & 15) * CPAD + (lane >> 4) * 8) * 2);
        uint32_t cph0 = 0, cph1 = 0;
        int it = 0;
        for (int tile = blockIdx.x; tile < NTILES; tile += GRID, ++it) {
            const int b = it & 1;
            const int x0 = (tile & 15) * 32, y0 = ((tile >> 4) & 31) * 16, n = tile >> 9;
            if (b == 0) { mbar_wait(mbF0, cph0); cph0 ^= 1; }
            else        { mbar_wait(mbF1, cph1); cph1 ^= 1; }
            const uint32_t fb = fbb + (uint32_t)(b * NS_SZ);

            float acc[4][2][4];
            #pragma unroll
            for (int i = 0; i < 4; ++i)
                #pragma unroll
                for (int nn = 0; nn < 2; ++nn)
                    #pragma unroll
                    for (int j = 0; j < 4; ++j) acc[i][nn][j] = 0.0f;

            #pragma unroll
            for (int kw = 0; kw < 3; ++kw) {
                uint32_t bf[3][2][2];
                #pragma unroll
                for (int dy = 0; dy < 3; ++dy)
                    #pragma unroll
                    for (int nn = 0; nn < 2; ++nn) {
                        uint2 v = Bs2[((dy * 3 + kw) * 2 + nn) * 32 + lane];
                        bf[dy][nn][0] = v.x;
                        bf[dy][nn][1] = v.y;
                    }
                #pragma unroll
                for (int xh = 0; xh < 2; ++xh) {
                    uint32_t F[4][4];
                    #pragma unroll
                    for (int q = 0; q < 4; ++q)
                        ldsm4(F[q][0], F[q][1], F[q][2], F[q][3],
                              fb + (uint32_t)(((2 * wrp + q) * NSX + xh * 16 + kw)
                                              * (CPAD * 2)));
                    #pragma unroll
                    for (int yl = 0; yl < 2; ++yl)
                        #pragma unroll
                        for (int dy = 0; dy < 3; ++dy) {
                            const int q = yl + dy;
                            const int i = yl * 2 + xh;
                            mma16816(acc[i][0], F[q][0], F[q][1], F[q][2], F[q][3],
                                     bf[dy][0][0], bf[dy][0][1]);
                            mma16816(acc[i][1], F[q][0], F[q][1], F[q][2], F[q][3],
                                     bf[dy][1][0], bf[dy][1][1]);
                        }
                }
            }
            if (elect_one()) mbar_arrive(b == 0 ? mbE0 : mbE1);

            // ---- direct-store epilogue ----
            #pragma unroll
            for (int i = 0; i < 4; ++i) {
                const int yloc = wrp * 2 + (i >> 1);
                const int xh   = i & 1;
                const int y  = y0 + yloc;
                const int xg = x0 + xh * 16 + g;
                #pragma unroll
                for (int nn = 0; nn < 2; ++nn) {
                    const int co = nn * 8 + cq;
                    float* op = out + ((size_t)(n * 16 + co) * HW + y) * HW + xg;
                    op[0]                   = acc[i][nn][0];
                    op[(size_t)HW * HW]     = acc[i][nn][1];
                    op[8]                   = acc[i][nn][2];
                    op[(size_t)HW * HW + 8] = acc[i][nn][3];
                }
            }
        }
    }
}

extern "C" void kernel_launch(void* const* d_in, const int* in_sizes, int n_in,
                              void* d_out, int out_size) {
    const float* x = (const float*)d_in[0];   // [8,16,512,512]
    const float* w = (const float*)d_in[1];   // [16,144]
    float* out = (float*)d_out;

    static int attr_done = 0;
    if (!attr_done) {
        cudaFuncSetAttribute(conv_mma_ws,
                             cudaFuncAttributeMaxDynamicSharedMemorySize, SM_TOTAL);
        attr_done = 1;
    }
    conv_mma_ws<<<GRID, NTHR, SM_TOTAL>>>(x, w, out);
}